// round 7
// baseline (speedup 1.0000x reference)
#include <cuda_runtime.h>
#include <cstdint>

#define HEADS 8
#define SEQ   4096
#define DQK   96
#define DV    64
#define ATTN_SCALE 0.17677669529663689f   // (256/8)^-0.5

// ---------------- scratch (device globals: no allocation allowed) ----------
// All three stored ALREADY tf32-rounded (rounded in proj epilogue), so the
// attention kernel feeds raw smem/gmem bits straight into mma — zero cvt.
__device__ float Qg[(size_t)HEADS * SEQ * DQK];   // [h][n][96], pre-scaled by ATTN_SCALE
__device__ float Kg[(size_t)HEADS * SEQ * DQK];   // [h][n][96]
__device__ float Vtg[(size_t)HEADS * DV * SEQ];   // [h*64+d][n]  (transposed V)

// ---------------- helpers --------------------------------------------------
__device__ __forceinline__ float to_tf32(float x) {
    uint32_t u;
    asm("cvt.rna.tf32.f32 %0, %1;" : "=r"(u) : "f"(x));
    return __uint_as_float(u);
}
__device__ __forceinline__ uint32_t fbits(float x) { return __float_as_uint(x); }

__device__ __forceinline__ void cp16(uint32_t dst_smem, const float* src) {
    asm volatile("cp.async.cg.shared.global [%0], [%1], 16;" :: "r"(dst_smem), "l"(src));
}
#define CP_COMMIT() asm volatile("cp.async.commit_group;" ::)
#define CP_WAIT1()  asm volatile("cp.async.wait_group 1;" ::)
#define CP_WAIT0()  asm volatile("cp.async.wait_group 0;" ::)

__device__ __forceinline__ uint32_t s2u(const void* p) {
    return (uint32_t)__cvta_generic_to_shared(p);
}

// D = A(16x8, tf32, row) * B(8x8, tf32, col) + D  (f32 accum)
__device__ __forceinline__ void mma8(float c[4],
                                     uint32_t a0, uint32_t a1, uint32_t a2, uint32_t a3,
                                     uint32_t b0, uint32_t b1) {
    asm volatile(
        "mma.sync.aligned.m16n8k8.row.col.f32.tf32.tf32.f32 "
        "{%0,%1,%2,%3}, {%4,%5,%6,%7}, {%8,%9}, {%0,%1,%2,%3};"
        : "+f"(c[0]), "+f"(c[1]), "+f"(c[2]), "+f"(c[3])
        : "r"(a0), "r"(a1), "r"(a2), "r"(a3), "r"(b0), "r"(b1));
}

// ---------------- merged projection GEMM (tf32 mma) ------------------------
#define PA_STRIDE 36
#define PW_STRIDE 72
#define PSTAGE    (128 * PA_STRIDE + 32 * PW_STRIDE)

__global__ __launch_bounds__(128) void proj_kernel(const float* __restrict__ qk,
                                                   const float* __restrict__ v_cls,
                                                   const float* __restrict__ Wqk,
                                                   const float* __restrict__ Wv) {
    extern __shared__ float sm[];

    const int  tid  = threadIdx.x;
    const int  w    = tid >> 5;
    const int  lane = tid & 31;
    const int  g    = lane >> 2;
    const int  t    = lane & 3;
    const bool isV  = blockIdx.x >= 24;
    const float* A  = isV ? v_cls : qk;
    const float* W  = isV ? Wv : Wqk;
    const int  K    = isV ? 512 : 768;
    const int  Nc   = isV ? 512 : 1536;
    const int  n0   = (isV ? (blockIdx.x - 24) : blockIdx.x) * 64;
    const int  m0   = blockIdx.y * 128;

    int ads[8]; size_t aoff[8];
#pragma unroll
    for (int j = 0; j < 8; j++) {
        int idx = tid + j * 128;
        int r = idx >> 3, c = (idx & 7) * 4;
        ads[j]  = r * PA_STRIDE + c;
        aoff[j] = (size_t)(m0 + r) * K + c;
    }
    int wds[4]; size_t woff[4];
#pragma unroll
    for (int j = 0; j < 4; j++) {
        int idx = tid + j * 128;
        int r = idx >> 4, c = (idx & 15) * 4;
        wds[j]  = r * PW_STRIDE + c;
        woff[j] = (size_t)r * Nc + n0 + c;
    }

    const uint32_t smem0 = s2u(sm);

    float acc[2][8][4];
#pragma unroll
    for (int r2 = 0; r2 < 2; r2++)
#pragma unroll
        for (int i = 0; i < 8; i++)
#pragma unroll
            for (int j = 0; j < 4; j++) acc[r2][i][j] = 0.f;

    const int T = K >> 5;

    auto issue = [&](int buf, int kt) {
        uint32_t Ab = smem0 + (uint32_t)(buf * PSTAGE) * 4u;
        uint32_t Wb = Ab + 128 * PA_STRIDE * 4u;
#pragma unroll
        for (int j = 0; j < 8; j++) cp16(Ab + ads[j] * 4u, &A[aoff[j] + kt]);
#pragma unroll
        for (int j = 0; j < 4; j++) cp16(Wb + wds[j] * 4u, &W[woff[j] + (size_t)kt * Nc]);
    };

    issue(0, 0); CP_COMMIT();

    for (int it = 0; it < T; it++) {
        if (it + 1 < T) { issue((it + 1) & 1, (it + 1) << 5); CP_COMMIT(); CP_WAIT1(); }
        else            { CP_WAIT0(); }
        __syncthreads();

        const float* As_ = sm + (it & 1) * PSTAGE;
        const float* Ws_ = As_ + 128 * PA_STRIDE;
        const int rbase = w * 32;

#pragma unroll
        for (int ks = 0; ks < 4; ks++) {
            uint32_t a[2][4];
#pragma unroll
            for (int r2 = 0; r2 < 2; r2++) {
                int rr = rbase + r2 * 16 + g;
                a[r2][0] = fbits(to_tf32(As_[rr * PA_STRIDE + ks * 8 + t]));
                a[r2][1] = fbits(to_tf32(As_[(rr + 8) * PA_STRIDE + ks * 8 + t]));
                a[r2][2] = fbits(to_tf32(As_[rr * PA_STRIDE + ks * 8 + t + 4]));
                a[r2][3] = fbits(to_tf32(As_[(rr + 8) * PA_STRIDE + ks * 8 + t + 4]));
            }
#pragma unroll
            for (int nf = 0; nf < 8; nf++) {
                uint32_t b0 = fbits(to_tf32(Ws_[(ks * 8 + t) * PW_STRIDE + nf * 8 + g]));
                uint32_t b1 = fbits(to_tf32(Ws_[(ks * 8 + t + 4) * PW_STRIDE + nf * 8 + g]));
                mma8(acc[0][nf], a[0][0], a[0][1], a[0][2], a[0][3], b0, b1);
                mma8(acc[1][nf], a[1][0], a[1][1], a[1][2], a[1][3], b0, b1);
            }
        }
        __syncthreads();
    }

#pragma unroll
    for (int r2 = 0; r2 < 2; r2++)
#pragma unroll
        for (int nf = 0; nf < 8; nf++)
#pragma unroll
            for (int j = 0; j < 4; j++) {
                int row = m0 + w * 32 + r2 * 16 + g + (j >> 1) * 8;
                int col = n0 + nf * 8 + 2 * t + (j & 1);
                float v = acc[r2][nf][j];
                if (!isV) {
                    if (col < 768) {
                        int h = col / 96, d = col - h * 96;
                        Qg[((size_t)h * SEQ + row) * DQK + d] = to_tf32(v * ATTN_SCALE);
                    } else {
                        int cc = col - 768;
                        int h = cc / 96, d = cc - h * 96;
                        Kg[((size_t)h * SEQ + row) * DQK + d] = to_tf32(v);
                    }
                } else {
                    Vtg[(size_t)col * SEQ + row] = to_tf32(v);
                }
            }
}

// ---------------- flash attention, 3-CTA/SM occupancy layout ---------------
// CTA = 64 q-rows x 1 head, 128 threads (warp = 16 rows). Bc = 64.
// SMEM 64 KB/CTA -> 3 CTAs/SM (12 warps): K double-buffered (2 x 6144 f),
// V single-buffered (4096 f), P tiles ALIAS the current K buffer (legal after
// the post-S barrier; K(it+2)'s cp.async only touches the other buffer).
// XOR swizzle (col ^= 4*(row&7)); no softmax max-tracking (|S| <~ 12).
#define BC 64
#define ATTN_SMEM (16384 * 4)    // 65536 B

__global__ __launch_bounds__(128, 3) void attn_kernel(const float* __restrict__ masks,
                                                      float* __restrict__ out) {
    extern __shared__ float sm[];

    const int tid  = threadIdx.x;
    const int w    = tid >> 5;
    const int lane = tid & 31;
    const int g    = lane >> 2;
    const int t    = lane & 3;
    const int h    = blockIdx.x;            // head fastest -> mask rows shared in L2
    const int q0   = blockIdx.y * 64;
    const int row0 = q0 + w * 16 + g;       // thread's first q-row (second = +8)
    const int swz  = g << 2;                // bank swizzle: col ^ 4g

    const float* Qbase = &Qg[(size_t)h * SEQ * DQK];
    const float* Kbase = &Kg[(size_t)h * SEQ * DQK];
    const float* Vbase = &Vtg[(size_t)h * DV * SEQ];
    const uint32_t smem0 = s2u(sm);

    // Q fragments (already tf32-rounded in gmem: raw bits)
    uint32_t qa[12][4];
#pragma unroll
    for (int ks = 0; ks < 12; ks++) {
        qa[ks][0] = fbits(__ldg(&Qbase[(size_t)row0 * DQK + ks * 8 + t]));
        qa[ks][1] = fbits(__ldg(&Qbase[(size_t)(row0 + 8) * DQK + ks * 8 + t]));
        qa[ks][2] = fbits(__ldg(&Qbase[(size_t)row0 * DQK + ks * 8 + t + 4]));
        qa[ks][3] = fbits(__ldg(&Qbase[(size_t)(row0 + 8) * DQK + ks * 8 + t + 4]));
    }

    float o[8][4];
#pragma unroll
    for (int i = 0; i < 8; i++)
#pragma unroll
        for (int j = 0; j < 4; j++) o[i][j] = 0.f;

    float z0 = 0.f, z1 = 0.f;     // exp-sums (quad-partial)
    float ws0 = 0.f, ws1 = 0.f;   // mask row-sums (quad-partial)

    // K tile: 64 keys x 96 f32 -> 12 cp16/thread.  V tile: 64 d x 64 -> 8.
    auto issueK = [&](int buf, int kt) {
        uint32_t Kb = smem0 + (buf ? 24576u : 0u);
#pragma unroll
        for (int j = 0; j < 12; j++) {
            int idx = tid + j * 128;
            int r = idx / 24, c = (idx % 24) * 4;
            cp16(Kb + (uint32_t)(r * 96 + (c ^ ((r & 7) << 2))) * 4u,
                 &Kbase[(size_t)(kt + r) * DQK + c]);
        }
    };
    auto issueV = [&](int kt) {
        uint32_t Vb = smem0 + 49152u;
#pragma unroll
        for (int j = 0; j < 8; j++) {
            int idx = tid + j * 128;
            int d0 = idx >> 4, k4 = (idx & 15) * 4;
            cp16(Vb + (uint32_t)(d0 * 64 + (k4 ^ ((d0 & 7) << 2))) * 4u,
                 &Vbase[(size_t)d0 * SEQ + kt + k4]);
        }
    };

    issueK(0, 0); CP_COMMIT();
    issueV(0);    CP_COMMIT();

#pragma unroll 1
    for (int it = 0; it < SEQ / BC; it++) {
        const int kt  = it * BC;
        const int buf = it & 1;
        if (it + 1 < SEQ / BC) { issueK(buf ^ 1, kt + BC); CP_COMMIT(); CP_WAIT1(); }
        else                   { CP_WAIT0(); }
        __syncthreads();

        const float* Ks = sm + (buf ? 6144 : 0);
        const float* Vs = sm + 12288;
        float* Pw = sm + (buf ? 6144 : 0) + w * 1024;  // alias current K buffer

        // ---- S = Q K^T (16x64 per warp) ----
        float s[8][4];
#pragma unroll
        for (int i = 0; i < 8; i++)
#pragma unroll
            for (int j = 0; j < 4; j++) s[i][j] = 0.f;
#pragma unroll
        for (int ks = 0; ks < 12; ks++) {
#pragma unroll
            for (int nf = 0; nf < 8; nf++) {
                const float* kr = &Ks[(nf * 8 + g) * 96];
                uint32_t b0 = fbits(kr[(ks * 8 + t) ^ swz]);
                uint32_t b1 = fbits(kr[(ks * 8 + t + 4) ^ swz]);
                mma8(s[nf], qa[ks][0], qa[ks][1], qa[ks][2], qa[ks][3], b0, b1);
            }
        }
        __syncthreads();   // all warps done reading Ks -> safe to overwrite with P

        // ---- pointwise softmax numerator * mask -> P (in old K buffer) ----
        {
            const float* m0p = &masks[(size_t)row0 * SEQ + kt];
            const float* m1p = m0p + (size_t)8 * SEQ;
            float* Pr0 = &Pw[g * 64];
            float* Pr1 = &Pw[(8 + g) * 64];
#pragma unroll
            for (int nf = 0; nf < 8; nf++) {
                float2 mv0 = __ldg(reinterpret_cast<const float2*>(&m0p[nf * 8 + 2 * t]));
                float2 mv1 = __ldg(reinterpret_cast<const float2*>(&m1p[nf * 8 + 2 * t]));
                float p00 = __expf(s[nf][0]);
                float p01 = __expf(s[nf][1]);
                float p10 = __expf(s[nf][2]);
                float p11 = __expf(s[nf][3]);
                z0 += p00 + p01;  z1 += p10 + p11;
                ws0 += mv0.x + mv0.y;  ws1 += mv1.x + mv1.y;
                const int pc = (nf * 8 + 2 * t) ^ swz;
                *reinterpret_cast<float2*>(&Pr0[pc]) =
                    make_float2(to_tf32(p00 * mv0.x), to_tf32(p01 * mv0.y));
                *reinterpret_cast<float2*>(&Pr1[pc]) =
                    make_float2(to_tf32(p10 * mv1.x), to_tf32(p11 * mv1.y));
            }
        }
        __syncwarp();   // own warp's P tile only

        // ---- O += P~ @ V ----
#pragma unroll
        for (int kq = 0; kq < 8; kq++) {
            const int c0 = (kq * 8 + t) ^ swz;
            const int c1 = (kq * 8 + t + 4) ^ swz;
            uint32_t a0 = fbits(Pw[g * 64 + c0]);
            uint32_t a1 = fbits(Pw[(8 + g) * 64 + c0]);
            uint32_t a2 = fbits(Pw[g * 64 + c1]);
            uint32_t a3 = fbits(Pw[(8 + g) * 64 + c1]);
#pragma unroll
            for (int nf = 0; nf < 8; nf++) {
                const float* vr = &Vs[(nf * 8 + g) * 64];
                uint32_t b0 = fbits(vr[c0]);
                uint32_t b1 = fbits(vr[c1]);
                mma8(o[nf], a0, a1, a2, a3, b0, b1);
            }
        }
        __syncthreads();   // all warps done with V (and P) before refill

        if (it + 1 < SEQ / BC) { issueV(kt + BC); CP_COMMIT(); }
    }

    // ---- final quad reductions + scaling: out = O / (Z * 8 * Wsum) ----
    z0 += __shfl_xor_sync(0xffffffffu, z0, 1);  z0 += __shfl_xor_sync(0xffffffffu, z0, 2);
    z1 += __shfl_xor_sync(0xffffffffu, z1, 1);  z1 += __shfl_xor_sync(0xffffffffu, z1, 2);
    ws0 += __shfl_xor_sync(0xffffffffu, ws0, 1); ws0 += __shfl_xor_sync(0xffffffffu, ws0, 2);
    ws1 += __shfl_xor_sync(0xffffffffu, ws1, 1); ws1 += __shfl_xor_sync(0xffffffffu, ws1, 2);
    const float inv0 = 1.f / (z0 * 8.f * ws0);
    const float inv1 = 1.f / (z1 * 8.f * ws1);

#pragma unroll
    for (int nf = 0; nf < 8; nf++) {
        const int col = h * 64 + nf * 8 + 2 * t;
        *reinterpret_cast<float2*>(&out[(size_t)row0 * 512 + col]) =
            make_float2(o[nf][0] * inv0, o[nf][1] * inv0);
        *reinterpret_cast<float2*>(&out[(size_t)(row0 + 8) * 512 + col]) =
            make_float2(o[nf][2] * inv1, o[nf][3] * inv1);
    }
}

// ---------------- launch ---------------------------------------------------
extern "C" void kernel_launch(void* const* d_in, const int* in_sizes, int n_in,
                              void* d_out, int out_size) {
    const float* qk    = (const float*)d_in[0];   // (1, 4096, 768)
    const float* v_cls = (const float*)d_in[1];   // (1, 4096, 512)
    const float* masks = (const float*)d_in[2];   // (1, 4096, 4096)
    const float* W_qk  = (const float*)d_in[3];   // (768, 1536)
    const float* W_v   = (const float*)d_in[4];   // (512, 512)
    float* out = (float*)d_out;                   // (1, 4096, 512)

    const int proj_smem = 2 * PSTAGE * (int)sizeof(float);
    cudaFuncSetAttribute(proj_kernel, cudaFuncAttributeMaxDynamicSharedMemorySize, proj_smem);
    proj_kernel<<<dim3(32, 32), 128, proj_smem>>>(qk, v_cls, W_qk, W_v);

    cudaFuncSetAttribute(attn_kernel, cudaFuncAttributeMaxDynamicSharedMemorySize, ATTN_SMEM);
    attn_kernel<<<dim3(HEADS, SEQ / 64), 128, ATTN_SMEM>>>(masks, out);
}

// round 8
// speedup vs baseline: 1.3128x; 1.3128x over previous
#include <cuda_runtime.h>
#include <cuda_fp16.h>
#include <cstdint>

#define HEADS 8
#define SEQ   4096
#define DQK   96
#define DV    64
#define ATTN_SCALE 0.17677669529663689f   // (256/8)^-0.5
#define P_SCALE 0.015625f                 // 2^-6 (overflow guard for fp16 P)

// ---------------- scratch (device globals: no allocation allowed) ----------
__device__ __half Qg[(size_t)HEADS * SEQ * DQK];   // [h][n][96] fp16, pre-scaled
__device__ __half Kg[(size_t)HEADS * SEQ * DQK];   // [h][n][96] fp16
__device__ __half Vtg[(size_t)HEADS * DV * SEQ];   // [h*64+d][n] fp16 (transposed V)
__device__ float  Op[(size_t)2 * SEQ * 512];       // split partial O (P_SCALE applied)
__device__ float  Zp[2 * HEADS * SEQ];             // split partial exp-sums
__device__ float  Wsp[2 * HEADS * SEQ];            // split partial mask row-sums

// ---------------- helpers --------------------------------------------------
__device__ __forceinline__ float to_tf32(float x) {
    uint32_t u;
    asm("cvt.rna.tf32.f32 %0, %1;" : "=r"(u) : "f"(x));
    return __uint_as_float(u);
}
__device__ __forceinline__ uint32_t fbits(float x) { return __float_as_uint(x); }

__device__ __forceinline__ void cp16(uint32_t dst_smem, const void* src) {
    asm volatile("cp.async.cg.shared.global [%0], [%1], 16;" :: "r"(dst_smem), "l"(src));
}
#define CP_COMMIT() asm volatile("cp.async.commit_group;" ::)
#define CP_WAIT1()  asm volatile("cp.async.wait_group 1;" ::)
#define CP_WAIT0()  asm volatile("cp.async.wait_group 0;" ::)

__device__ __forceinline__ uint32_t s2u(const void* p) {
    return (uint32_t)__cvta_generic_to_shared(p);
}

// tf32: D(16x8) += A(16x8) * B(8x8)
__device__ __forceinline__ void mma8(float c[4],
                                     uint32_t a0, uint32_t a1, uint32_t a2, uint32_t a3,
                                     uint32_t b0, uint32_t b1) {
    asm volatile(
        "mma.sync.aligned.m16n8k8.row.col.f32.tf32.tf32.f32 "
        "{%0,%1,%2,%3}, {%4,%5,%6,%7}, {%8,%9}, {%0,%1,%2,%3};"
        : "+f"(c[0]), "+f"(c[1]), "+f"(c[2]), "+f"(c[3])
        : "r"(a0), "r"(a1), "r"(a2), "r"(a3), "r"(b0), "r"(b1));
}
// fp16: D(16x8,f32) += A(16x16,f16) * B(16x8,f16)
__device__ __forceinline__ void mma16(float c[4],
                                      uint32_t a0, uint32_t a1, uint32_t a2, uint32_t a3,
                                      uint32_t b0, uint32_t b1) {
    asm volatile(
        "mma.sync.aligned.m16n8k16.row.col.f32.f16.f16.f32 "
        "{%0,%1,%2,%3}, {%4,%5,%6,%7}, {%8,%9}, {%0,%1,%2,%3};"
        : "+f"(c[0]), "+f"(c[1]), "+f"(c[2]), "+f"(c[3])
        : "r"(a0), "r"(a1), "r"(a2), "r"(a3), "r"(b0), "r"(b1));
}

__device__ __forceinline__ uint32_t pack_h2(float lo, float hi) {
    __half2 h = __floats2half2_rn(lo, hi);
    return *reinterpret_cast<uint32_t*>(&h);
}

// ---------------- merged projection GEMM (tf32 mma, fp16 epilogue) ---------
#define PA_STRIDE 36
#define PW_STRIDE 72
#define PSTAGE    (128 * PA_STRIDE + 32 * PW_STRIDE)

__global__ __launch_bounds__(128) void proj_kernel(const float* __restrict__ qk,
                                                   const float* __restrict__ v_cls,
                                                   const float* __restrict__ Wqk,
                                                   const float* __restrict__ Wv) {
    extern __shared__ float sm[];

    const int  tid  = threadIdx.x;
    const int  w    = tid >> 5;
    const int  lane = tid & 31;
    const int  g    = lane >> 2;
    const int  t    = lane & 3;
    const bool isV  = blockIdx.x >= 24;
    const float* A  = isV ? v_cls : qk;
    const float* W  = isV ? Wv : Wqk;
    const int  K    = isV ? 512 : 768;
    const int  Nc   = isV ? 512 : 1536;
    const int  n0   = (isV ? (blockIdx.x - 24) : blockIdx.x) * 64;
    const int  m0   = blockIdx.y * 128;

    int ads[8]; size_t aoff[8];
#pragma unroll
    for (int j = 0; j < 8; j++) {
        int idx = tid + j * 128;
        int r = idx >> 3, c = (idx & 7) * 4;
        ads[j]  = r * PA_STRIDE + c;
        aoff[j] = (size_t)(m0 + r) * K + c;
    }
    int wds[4]; size_t woff[4];
#pragma unroll
    for (int j = 0; j < 4; j++) {
        int idx = tid + j * 128;
        int r = idx >> 4, c = (idx & 15) * 4;
        wds[j]  = r * PW_STRIDE + c;
        woff[j] = (size_t)r * Nc + n0 + c;
    }

    const uint32_t smem0 = s2u(sm);

    float acc[2][8][4];
#pragma unroll
    for (int r2 = 0; r2 < 2; r2++)
#pragma unroll
        for (int i = 0; i < 8; i++)
#pragma unroll
            for (int j = 0; j < 4; j++) acc[r2][i][j] = 0.f;

    const int T = K >> 5;

    auto issue = [&](int buf, int kt) {
        uint32_t Ab = smem0 + (uint32_t)(buf * PSTAGE) * 4u;
        uint32_t Wb = Ab + 128 * PA_STRIDE * 4u;
#pragma unroll
        for (int j = 0; j < 8; j++) cp16(Ab + ads[j] * 4u, &A[aoff[j] + kt]);
#pragma unroll
        for (int j = 0; j < 4; j++) cp16(Wb + wds[j] * 4u, &W[woff[j] + (size_t)kt * Nc]);
    };

    issue(0, 0); CP_COMMIT();

    for (int it = 0; it < T; it++) {
        if (it + 1 < T) { issue((it + 1) & 1, (it + 1) << 5); CP_COMMIT(); CP_WAIT1(); }
        else            { CP_WAIT0(); }
        __syncthreads();

        const float* As_ = sm + (it & 1) * PSTAGE;
        const float* Ws_ = As_ + 128 * PA_STRIDE;
        const int rbase = w * 32;

#pragma unroll
        for (int ks = 0; ks < 4; ks++) {
            uint32_t a[2][4];
#pragma unroll
            for (int r2 = 0; r2 < 2; r2++) {
                int rr = rbase + r2 * 16 + g;
                a[r2][0] = fbits(to_tf32(As_[rr * PA_STRIDE + ks * 8 + t]));
                a[r2][1] = fbits(to_tf32(As_[(rr + 8) * PA_STRIDE + ks * 8 + t]));
                a[r2][2] = fbits(to_tf32(As_[rr * PA_STRIDE + ks * 8 + t + 4]));
                a[r2][3] = fbits(to_tf32(As_[(rr + 8) * PA_STRIDE + ks * 8 + t + 4]));
            }
#pragma unroll
            for (int nf = 0; nf < 8; nf++) {
                uint32_t b0 = fbits(to_tf32(Ws_[(ks * 8 + t) * PW_STRIDE + nf * 8 + g]));
                uint32_t b1 = fbits(to_tf32(Ws_[(ks * 8 + t + 4) * PW_STRIDE + nf * 8 + g]));
                mma8(acc[0][nf], a[0][0], a[0][1], a[0][2], a[0][3], b0, b1);
                mma8(acc[1][nf], a[1][0], a[1][1], a[1][2], a[1][3], b0, b1);
            }
        }
        __syncthreads();
    }

    // epilogue: store fp16 (11-bit mantissa, same rounding class as tf32)
#pragma unroll
    for (int r2 = 0; r2 < 2; r2++)
#pragma unroll
        for (int nf = 0; nf < 8; nf++)
#pragma unroll
            for (int j = 0; j < 4; j++) {
                int row = m0 + w * 32 + r2 * 16 + g + (j >> 1) * 8;
                int col = n0 + nf * 8 + 2 * t + (j & 1);
                float v = acc[r2][nf][j];
                if (!isV) {
                    if (col < 768) {
                        int h = col / 96, d = col - h * 96;
                        Qg[((size_t)h * SEQ + row) * DQK + d] = __float2half_rn(v * ATTN_SCALE);
                    } else {
                        int cc = col - 768;
                        int h = cc / 96, d = cc - h * 96;
                        Kg[((size_t)h * SEQ + row) * DQK + d] = __float2half_rn(v);
                    }
                } else {
                    Vtg[(size_t)col * SEQ + row] = __float2half_rn(v);
                }
            }
}

// ---------------- fp16 flash attention, key-split x2 -----------------------
// CTA = 128 q-rows x 1 head x half-the-keys; 128 threads, warp = 32 rows
// (M-blocked, su=2). Bc=64, K+V double-buffered cp.async, no max-tracking.
// SMEM in 32-bit words (half2): K rows 52 w, V rows 36 w, P rows 36 w —
// all hot LDS/STS conflict-free (bank = 4g+t or 20g+t patterns).
#define BC 64
#define KW0 0
#define KW1 3328
#define VW0 6656
#define VW1 8960
#define PW0 11264          // + w*1152
#define ATTN_SMEM ((11264 + 4 * 1152) * 4)    // 63488 B -> 3 CTAs/SM

__global__ __launch_bounds__(128, 3) void attn_kernel(const float* __restrict__ masks) {
    extern __shared__ uint32_t smw[];

    const int tid   = threadIdx.x;
    const int w     = tid >> 5;
    const int lane  = tid & 31;
    const int g     = lane >> 2;
    const int t     = lane & 3;
    const int h     = blockIdx.x;
    const int q0    = blockIdx.y * 128;
    const int split = blockIdx.z;
    const int kt0   = split * (SEQ / 2);
    const int rb    = q0 + w * 32;          // warp's first q-row
    const uint32_t smem0 = s2u(smw);

    const __half* Kh = &Kg[(size_t)h * SEQ * DQK];
    const __half* Vh = &Vtg[(size_t)h * DV * SEQ];
    const uint32_t* Qw = reinterpret_cast<const uint32_t*>(&Qg[(size_t)h * SEQ * DQK]);
    uint32_t* Pw = smw + PW0 + w * 1152;

    // Q A-fragments: [su][ks](a0..a3), packed fp16 words (row stride 48 words)
    uint32_t qa[2][6][4];
#pragma unroll
    for (int su = 0; su < 2; su++) {
        const int r = rb + su * 16 + g;
#pragma unroll
        for (int ks = 0; ks < 6; ks++) {
            qa[su][ks][0] = __ldg(&Qw[(size_t)r * 48 + ks * 8 + t]);
            qa[su][ks][1] = __ldg(&Qw[(size_t)(r + 8) * 48 + ks * 8 + t]);
            qa[su][ks][2] = __ldg(&Qw[(size_t)r * 48 + ks * 8 + t + 4]);
            qa[su][ks][3] = __ldg(&Qw[(size_t)(r + 8) * 48 + ks * 8 + t + 4]);
        }
    }

    float o[2][8][4];
#pragma unroll
    for (int su = 0; su < 2; su++)
#pragma unroll
        for (int i = 0; i < 8; i++)
#pragma unroll
            for (int j = 0; j < 4; j++) o[su][i][j] = 0.f;

    float zz[4]  = {0.f, 0.f, 0.f, 0.f};
    float wss[4] = {0.f, 0.f, 0.f, 0.f};

    // K tile: 64 keys x 96 fp16 = 768 16B chunks (6/thr); V: 64 d x 64 = 512 (4/thr)
    auto issue = [&](int buf, int kt) {
        uint32_t Kb = smem0 + (buf ? KW1 : KW0) * 4u;
        uint32_t Vb = smem0 + (buf ? VW1 : VW0) * 4u;
#pragma unroll
        for (int j = 0; j < 6; j++) {
            int idx = tid + j * 128;
            int r = idx / 12, c = idx % 12;
            cp16(Kb + (uint32_t)(r * 52 + c * 4) * 4u, Kh + (size_t)(kt + r) * DQK + c * 8);
        }
#pragma unroll
        for (int j = 0; j < 4; j++) {
            int idx = tid + j * 128;
            int d0 = idx >> 3, c = idx & 7;
            cp16(Vb + (uint32_t)(d0 * 36 + c * 4) * 4u, Vh + (size_t)d0 * SEQ + kt + c * 8);
        }
    };

    issue(0, kt0); CP_COMMIT();

#pragma unroll 1
    for (int it = 0; it < SEQ / (2 * BC); it++) {
        const int kt  = kt0 + it * BC;
        const int buf = it & 1;

        CP_WAIT0();
        __syncthreads();    // tile landed; all warps done with prev buffers
        if (it + 1 < SEQ / (2 * BC)) { issue(buf ^ 1, kt + BC); CP_COMMIT(); }

        const uint32_t* Ks = smw + (buf ? KW1 : KW0);
        const uint32_t* Vs = smw + (buf ? VW1 : VW0);

        // ---- S = Q K^T + softmax, streamed in 2 chunks of 4 key-octets ----
#pragma unroll
        for (int c2 = 0; c2 < 2; c2++) {
            float s[2][4][4];
#pragma unroll
            for (int su = 0; su < 2; su++)
#pragma unroll
                for (int i = 0; i < 4; i++)
#pragma unroll
                    for (int j = 0; j < 4; j++) s[su][i][j] = 0.f;
#pragma unroll
            for (int ks = 0; ks < 6; ks++) {
#pragma unroll
                for (int nfl = 0; nfl < 4; nfl++) {
                    const int nf = c2 * 4 + nfl;
                    uint32_t b0 = Ks[(nf * 8 + g) * 52 + ks * 8 + t];
                    uint32_t b1 = Ks[(nf * 8 + g) * 52 + ks * 8 + t + 4];
                    mma16(s[0][nfl], qa[0][ks][0], qa[0][ks][1], qa[0][ks][2], qa[0][ks][3], b0, b1);
                    mma16(s[1][nfl], qa[1][ks][0], qa[1][ks][1], qa[1][ks][2], qa[1][ks][3], b0, b1);
                }
            }
            // pointwise softmax numerator * mask -> fp16 P (C cols = 2t,2t+1)
#pragma unroll
            for (int su = 0; su < 2; su++) {
                const float* m0p = &masks[(size_t)(rb + su * 16 + g) * SEQ + kt];
                const float* m1p = m0p + (size_t)8 * SEQ;
#pragma unroll
                for (int nfl = 0; nfl < 4; nfl++) {
                    const int nf = c2 * 4 + nfl;
                    float2 mv0 = __ldg(reinterpret_cast<const float2*>(&m0p[nf * 8 + 2 * t]));
                    float2 mv1 = __ldg(reinterpret_cast<const float2*>(&m1p[nf * 8 + 2 * t]));
                    float e00 = __expf(s[su][nfl][0]);
                    float e01 = __expf(s[su][nfl][1]);
                    float e10 = __expf(s[su][nfl][2]);
                    float e11 = __expf(s[su][nfl][3]);
                    zz[su * 2 + 0] += e00 + e01;  zz[su * 2 + 1] += e10 + e11;
                    wss[su * 2 + 0] += mv0.x + mv0.y;  wss[su * 2 + 1] += mv1.x + mv1.y;
                    Pw[(su * 16 + g) * 36 + nf * 4 + t] =
                        pack_h2(e00 * mv0.x * P_SCALE, e01 * mv0.y * P_SCALE);
                    Pw[(su * 16 + 8 + g) * 36 + nf * 4 + t] =
                        pack_h2(e10 * mv1.x * P_SCALE, e11 * mv1.y * P_SCALE);
                }
            }
        }
        __syncwarp();   // own warp's P tile only

        // ---- O += P~ @ V ----
#pragma unroll
        for (int kq = 0; kq < 4; kq++) {
            uint32_t a[2][4];
#pragma unroll
            for (int su = 0; su < 2; su++) {
                a[su][0] = Pw[(su * 16 + g) * 36 + kq * 8 + t];
                a[su][1] = Pw[(su * 16 + 8 + g) * 36 + kq * 8 + t];
                a[su][2] = Pw[(su * 16 + g) * 36 + kq * 8 + t + 4];
                a[su][3] = Pw[(su * 16 + 8 + g) * 36 + kq * 8 + t + 4];
            }
#pragma unroll
            for (int nf = 0; nf < 8; nf++) {
                uint32_t b0 = Vs[(nf * 8 + g) * 36 + kq * 8 + t];
                uint32_t b1 = Vs[(nf * 8 + g) * 36 + kq * 8 + t + 4];
                mma16(o[0][nf], a[0][0], a[0][1], a[0][2], a[0][3], b0, b1);
                mma16(o[1][nf], a[1][0], a[1][1], a[1][2], a[1][3], b0, b1);
            }
        }
    }

    // ---- epilogue: quad-reduce z/ws, write partials ----
#pragma unroll
    for (int r = 0; r < 4; r++) {
        zz[r]  += __shfl_xor_sync(0xffffffffu, zz[r], 1);
        zz[r]  += __shfl_xor_sync(0xffffffffu, zz[r], 2);
        wss[r] += __shfl_xor_sync(0xffffffffu, wss[r], 1);
        wss[r] += __shfl_xor_sync(0xffffffffu, wss[r], 2);
    }
    if (t == 0) {
        const size_t zb = (size_t)split * HEADS * SEQ + (size_t)h * SEQ;
#pragma unroll
        for (int su = 0; su < 2; su++) {
            Zp[zb + rb + su * 16 + g]      = zz[su * 2 + 0];
            Zp[zb + rb + su * 16 + 8 + g]  = zz[su * 2 + 1];
            Wsp[zb + rb + su * 16 + g]     = wss[su * 2 + 0];
            Wsp[zb + rb + su * 16 + 8 + g] = wss[su * 2 + 1];
        }
    }
    float* Ob = &Op[(size_t)split * SEQ * 512];
#pragma unroll
    for (int su = 0; su < 2; su++) {
        const int r0 = rb + su * 16 + g;
#pragma unroll
        for (int nf = 0; nf < 8; nf++) {
            const int col = h * 64 + nf * 8 + 2 * t;
            *reinterpret_cast<float2*>(&Ob[(size_t)r0 * 512 + col]) =
                make_float2(o[su][nf][0], o[su][nf][1]);
            *reinterpret_cast<float2*>(&Ob[(size_t)(r0 + 8) * 512 + col]) =
                make_float2(o[su][nf][2], o[su][nf][3]);
        }
    }
}

// ---------------- combine splits: out = 8*(O0+O1)/((z0+z1)*(ws0+ws1)) ------
// 8 = P_SCALE^-1 / (H=8).  4096*512 elements, float4 per thread.
__global__ __launch_bounds__(256) void combine_kernel(float* __restrict__ out) {
    const int idx = blockIdx.x * 256 + threadIdx.x;   // 0 .. 4096*128-1
    const int n = idx >> 7;
    const int c = (idx & 127) * 4;
    const int h = c >> 6;
    const float4 a = *reinterpret_cast<const float4*>(&Op[(size_t)n * 512 + c]);
    const float4 b = *reinterpret_cast<const float4*>(&Op[(size_t)SEQ * 512 + (size_t)n * 512 + c]);
    const size_t zi = (size_t)h * SEQ + n;
    const float z  = Zp[zi]  + Zp[(size_t)HEADS * SEQ + zi];
    const float ws = Wsp[zi] + Wsp[(size_t)HEADS * SEQ + zi];
    const float inv = 8.f / (z * ws);
    float4 r;
    r.x = (a.x + b.x) * inv;  r.y = (a.y + b.y) * inv;
    r.z = (a.z + b.z) * inv;  r.w = (a.w + b.w) * inv;
    *reinterpret_cast<float4*>(&out[(size_t)n * 512 + c]) = r;
}

// ---------------- launch ---------------------------------------------------
extern "C" void kernel_launch(void* const* d_in, const int* in_sizes, int n_in,
                              void* d_out, int out_size) {
    const float* qk    = (const float*)d_in[0];   // (1, 4096, 768)
    const float* v_cls = (const float*)d_in[1];   // (1, 4096, 512)
    const float* masks = (const float*)d_in[2];   // (1, 4096, 4096)
    const float* W_qk  = (const float*)d_in[3];   // (768, 1536)
    const float* W_v   = (const float*)d_in[4];   // (512, 512)
    float* out = (float*)d_out;                   // (1, 4096, 512)

    const int proj_smem = 2 * PSTAGE * (int)sizeof(float);
    cudaFuncSetAttribute(proj_kernel, cudaFuncAttributeMaxDynamicSharedMemorySize, proj_smem);
    proj_kernel<<<dim3(32, 32), 128, proj_smem>>>(qk, v_cls, W_qk, W_v);

    cudaFuncSetAttribute(attn_kernel, cudaFuncAttributeMaxDynamicSharedMemorySize, ATTN_SMEM);
    attn_kernel<<<dim3(HEADS, SEQ / 128, 2), 128, ATTN_SMEM>>>(masks);

    combine_kernel<<<(SEQ * 128) / 256, 256>>>(out);
}